// round 6
// baseline (speedup 1.0000x reference)
#include <cuda_runtime.h>
#include <cuda_bf16.h>

// out[n,c] = 0.05f * sum_{m,t,v} x[n,m,c,t,v]
// (VQ assignments in the reference conserve per-sample totals at every
//  pooling level, so the output is independent of the prototypes.)
//
// R6: stream-locality experiment. Each block owns (n, c-pair) and reads its
// data as two SEQUENTIAL contiguous 51.2KB regions (m=0 phase, then m=1
// phase) instead of two interleaved streams. Concurrent DRAM streams drop
// from 1776 x 25.6KB to 888 x 51.2KB -> fewer row-buffer conflicts.
// Inner shape identical to the proven R2 body (10 float4 in flight).

#define N_SAMP 32
#define M_DIM  2
#define C_DIM  256
#define TV     6400            // T*V
#define BT     320
#define PAIR4  3200            // float4 in a contiguous 2-c slice (2*1600)

__global__ __launch_bounds__(BT)
void pretrain_neck_reduce(const float* __restrict__ x, float* __restrict__ out) {
    const int bid   = blockIdx.x;          // [0, 32*128)
    const int n     = bid >> 7;            // / 128
    const int cpair = bid & 127;
    const int c0    = cpair * 2;

    const int tid = threadIdx.x;

    float s0 = 0.f, s1 = 0.f;              // sums for c0, c0+1

    #pragma unroll
    for (int m = 0; m < M_DIM; ++m) {
        // contiguous 12800 floats = [c0 slice][c0+1 slice] for this (n,m)
        const float4* p = reinterpret_cast<const float4*>(
            x + ((size_t)(n * M_DIM + m) * C_DIM + c0) * (size_t)TV);

        float4 v[10];
        #pragma unroll
        for (int j = 0; j < 10; ++j)
            v[j] = __ldcs(p + tid + j * BT);   // i = tid + j*320 in [0,3200)

        // j <= 4  -> i < 1600  (c0) ;  j >= 5 -> i >= 1600 (c0+1)
        #pragma unroll
        for (int j = 0; j < 5; ++j) {
            s0 += (v[j].x + v[j].y) + (v[j].z + v[j].w);
            s1 += (v[j + 5].x + v[j + 5].y) + (v[j + 5].z + v[j + 5].w);
        }
    }

    // warp reduce both sums
    #pragma unroll
    for (int off = 16; off > 0; off >>= 1) {
        s0 += __shfl_down_sync(0xFFFFFFFFu, s0, off);
        s1 += __shfl_down_sync(0xFFFFFFFFu, s1, off);
    }

    __shared__ float warp_sums[10][2];
    const int lane = tid & 31;
    const int wid  = tid >> 5;
    if (lane == 0) { warp_sums[wid][0] = s0; warp_sums[wid][1] = s1; }
    __syncthreads();

    if (wid == 0) {
        float t0 = (lane < 10) ? warp_sums[lane][0] : 0.f;
        float t1 = (lane < 10) ? warp_sums[lane][1] : 0.f;
        #pragma unroll
        for (int off = 8; off > 0; off >>= 1) {
            t0 += __shfl_down_sync(0xFFFFFFFFu, t0, off);
            t1 += __shfl_down_sync(0xFFFFFFFFu, t1, off);
        }
        if (lane == 0) {
            const int o = n * C_DIM + c0;
            out[o]     = t0 * 0.05f;      // (1/M)*(1/Kl)
            out[o + 1] = t1 * 0.05f;
        }
    }
}

extern "C" void kernel_launch(void* const* d_in, const int* in_sizes, int n_in,
                              void* d_out, int out_size) {
    const float* x = (const float*)d_in[0];   // [N, M, C, T, V] fp32
    float* out = (float*)d_out;               // [N, C] fp32
    (void)in_sizes; (void)n_in; (void)out_size;
    pretrain_neck_reduce<<<N_SAMP * (C_DIM / 2), BT>>>(x, out);
}